// round 2
// baseline (speedup 1.0000x reference)
#include <cuda_runtime.h>

// HMM forward algorithm, fp32, FFMA2 (packed f32x2) CUDA-core implementation.
// Shapes: UNITS=256, N=64, S=4, BATCH=64, T=1024.
// Inputs (metadata order): inputs[64,1024,4] f32, transition[256,64,64] f32,
//                          emission[256,64,4] f32, init[256,64] f32.
// Output: [64,1024,256] f32 cumulative log-likelihood.
//
// Grid: 256 blocks (one per unit u), 128 threads.
// Thread tile: 8 batches x 4 states. alpha kept state-major in smem so
// ld.shared.v2.b64 gives batch-pair f32x2 operands directly.

#define NU 256
#define NN 64
#define NS 4
#define NB 64
#define NT 1024

typedef unsigned long long f2;  // packed f32x2 in a .b64 register pair

__device__ __forceinline__ f2 pack2(float a, float b) {
    f2 r; asm("mov.b64 %0, {%1, %2};" : "=l"(r) : "f"(a), "f"(b)); return r;
}
__device__ __forceinline__ void unpack2(f2 v, float& a, float& b) {
    asm("mov.b64 {%0, %1}, %2;" : "=f"(a), "=f"(b) : "l"(v));
}
__device__ __forceinline__ f2 fma2(f2 a, f2 b, f2 c) {
    f2 d; asm("fma.rn.f32x2 %0, %1, %2, %3;" : "=l"(d) : "l"(a), "l"(b), "l"(c)); return d;
}

__global__ void __launch_bounds__(128) hmm_fwd_kernel(
    const float* __restrict__ x,      // [B, T, S]
    const float* __restrict__ trans,  // [U, N, N]
    const float* __restrict__ emis,   // [U, N, S]
    const float* __restrict__ initk,  // [U, N]
    float* __restrict__ out)          // [B, T, U]
{
    __shared__ float  A_sh[NN * NN];      // softmaxed transition, [i][j], 16 KB
    __shared__ float  alphaT[NN * NB];    // alpha, state-major [i][b], 16 KB
    __shared__ float4 x_sh[2][NB];        // double-buffered x_t, [b] -> 4 channels
    __shared__ float  B_sh[NN][NS];       // softmaxed emission
    __shared__ float  I_sh[NN];           // softmaxed init
    __shared__ float  IsumInv;

    const int tid  = threadIdx.x;
    const int u    = blockIdx.x;
    const int jgrp = tid & 15;    // 0..15 -> states j0..j0+3
    const int bgrp = tid >> 4;    // 0..7  -> batches b0..b0+7
    const int j0   = jgrp * 4;
    const int b0   = bgrp * 8;

    // ---------------- setup: load params + softmax ----------------
    const float* Tu = trans + u * NN * NN;
    for (int idx = tid; idx < NN * NN; idx += 128) A_sh[idx] = Tu[idx];

    if (tid < NN) {
        // emission softmax over S=4
        const float* Eu = emis + (u * NN + tid) * NS;
        float e0 = expf(Eu[0]), e1 = expf(Eu[1]), e2 = expf(Eu[2]), e3 = expf(Eu[3]);
        float s = (e0 + e1) + (e2 + e3);
        float r = 1.0f / s;
        B_sh[tid][0] = e0 * r; B_sh[tid][1] = e1 * r;
        B_sh[tid][2] = e2 * r; B_sh[tid][3] = e3 * r;
        // init: exp only (normalize after block-wide sum)
        I_sh[tid] = expf(initk[u * NN + tid]);
        // stage x_0
        x_sh[0][tid] = *(const float4*)(x + (size_t)tid * NT * NS);
    }
    __syncthreads();

    if (tid < NN) {
        // row softmax of transition row tid (over j)
        float s = 0.0f;
        #pragma unroll 8
        for (int j = 0; j < NN; ++j) {
            float e = expf(A_sh[tid * NN + j]);
            A_sh[tid * NN + j] = e;
            s += e;
        }
        float r = 1.0f / s;
        #pragma unroll 8
        for (int j = 0; j < NN; ++j) A_sh[tid * NN + j] *= r;
    }
    if (tid == 0) {
        float s = 0.0f;
        #pragma unroll 8
        for (int k = 0; k < NN; ++k) s += I_sh[k];
        IsumInv = 1.0f / s;
    }
    __syncthreads();
    if (tid < NN) I_sh[tid] *= IsumInv;
    __syncthreads();

    // per-thread constant registers
    float Breg[4][4];
    #pragma unroll
    for (int jj = 0; jj < 4; ++jj)
        #pragma unroll
        for (int c = 0; c < 4; ++c) Breg[jj][c] = B_sh[j0 + jj][c];
    float Ireg[4];
    #pragma unroll
    for (int jj = 0; jj < 4; ++jj) Ireg[jj] = I_sh[j0 + jj];

    float ll[8];
    #pragma unroll
    for (int k = 0; k < 8; ++k) ll[k] = 0.0f;

    const unsigned alpBase =
        (unsigned)__cvta_generic_to_shared(alphaT) + (unsigned)(b0 * 4);

    // ---------------- time loop ----------------
    for (int t = 0; t < NT; ++t) {
        // prefetch x_{t+1} into the other buffer (consumed next step, after syncs)
        if (tid < NB && (t + 1) < NT)
            x_sh[(t + 1) & 1][tid] =
                *(const float4*)(x + ((size_t)tid * NT + (t + 1)) * NS);

        f2 acc[4][4];  // [batch-pair][state jj]
        if (t == 0) {
            // R = I (is_init path; alpha = 0)
            #pragma unroll
            for (int bp = 0; bp < 4; ++bp)
                #pragma unroll
                for (int jj = 0; jj < 4; ++jj) acc[bp][jj] = pack2(Ireg[jj], Ireg[jj]);
        } else {
            #pragma unroll
            for (int bp = 0; bp < 4; ++bp)
                #pragma unroll
                for (int jj = 0; jj < 4; ++jj) acc[bp][jj] = 0ull;

            // R[b][j] = sum_i alpha[i][b] * A[i][j]
            #pragma unroll 16
            for (int i = 0; i < NN; ++i) {
                float4 Ar = *(const float4*)&A_sh[i * NN + j0];
                f2 av[4];
                unsigned ad = alpBase + (unsigned)(i * (NB * 4));
                asm("ld.shared.v2.b64 {%0, %1}, [%2];"
                    : "=l"(av[0]), "=l"(av[1]) : "r"(ad));
                asm("ld.shared.v2.b64 {%0, %1}, [%2];"
                    : "=l"(av[2]), "=l"(av[3]) : "r"(ad + 16));
                f2 Ad[4];
                Ad[0] = pack2(Ar.x, Ar.x); Ad[1] = pack2(Ar.y, Ar.y);
                Ad[2] = pack2(Ar.z, Ar.z); Ad[3] = pack2(Ar.w, Ar.w);
                #pragma unroll
                for (int bp = 0; bp < 4; ++bp)
                    #pragma unroll
                    for (int jj = 0; jj < 4; ++jj)
                        acc[bp][jj] = fma2(av[bp], Ad[jj], acc[bp][jj]);
            }
        }

        // ---------------- epilogue ----------------
        float s[8];
        float fw[8][4];
        #pragma unroll
        for (int bp = 0; bp < 4; ++bp) {
            float4 xa = x_sh[t & 1][b0 + 2 * bp];
            float4 xb = x_sh[t & 1][b0 + 2 * bp + 1];
            float sa = 0.0f, sb = 0.0f;
            #pragma unroll
            for (int jj = 0; jj < 4; ++jj) {
                float r0, r1; unpack2(acc[bp][jj], r0, r1);
                float ea = (Breg[jj][0] * xa.x + Breg[jj][1] * xa.y) +
                           (Breg[jj][2] * xa.z + Breg[jj][3] * xa.w);
                float eb = (Breg[jj][0] * xb.x + Breg[jj][1] * xb.y) +
                           (Breg[jj][2] * xb.z + Breg[jj][3] * xb.w);
                float f0 = ea * r0, f1 = eb * r1;
                fw[2 * bp][jj]     = f0;
                fw[2 * bp + 1][jj] = f1;
                sa += f0; sb += f1;
            }
            s[2 * bp] = sa; s[2 * bp + 1] = sb;
        }

        // butterfly reduce over the 16 jgroups (lane bits 0..3); bit-exact per lane
        #pragma unroll
        for (int m = 1; m < 16; m <<= 1)
            #pragma unroll
            for (int k = 0; k < 8; ++k)
                s[k] += __shfl_xor_sync(0xffffffffu, s[k], m);

        // log-likelihood update + output (one writer group per batch row)
        if (jgrp == 0) {
            #pragma unroll
            for (int k = 0; k < 8; ++k) {
                ll[k] += __logf(s[k]);
                out[((size_t)(b0 + k) * NT + t) * NU + u] = ll[k];
            }
        }

        float ri[8];
        #pragma unroll
        for (int k = 0; k < 8; ++k) ri[k] = __fdividef(1.0f, s[k]);

        __syncthreads();  // all alphaT readers done
        #pragma unroll
        for (int jj = 0; jj < 4; ++jj) {
            *(float4*)&alphaT[(j0 + jj) * NB + b0] =
                make_float4(fw[0][jj] * ri[0], fw[1][jj] * ri[1],
                            fw[2][jj] * ri[2], fw[3][jj] * ri[3]);
            *(float4*)&alphaT[(j0 + jj) * NB + b0 + 4] =
                make_float4(fw[4][jj] * ri[4], fw[5][jj] * ri[5],
                            fw[6][jj] * ri[6], fw[7][jj] * ri[7]);
        }
        __syncthreads();  // alphaT visible for next step
    }
}

extern "C" void kernel_launch(void* const* d_in, const int* in_sizes, int n_in,
                              void* d_out, int out_size) {
    const float* x     = (const float*)d_in[0];  // [64,1024,4]
    const float* trans = (const float*)d_in[1];  // [256,64,64]
    const float* emis  = (const float*)d_in[2];  // [256,64,4]
    const float* initk = (const float*)d_in[3];  // [256,64]
    float* out = (float*)d_out;                  // [64,1024,256]
    (void)in_sizes; (void)n_in; (void)out_size;

    hmm_fwd_kernel<<<NU, 128>>>(x, trans, emis, initk, out);
}